// round 8
// baseline (speedup 1.0000x reference)
#include <cuda_runtime.h>
#include <cuda_fp16.h>
#include <math.h>
#include <stdint.h>

#define B_   512
#define T_   256
#define C_   384
#define H_   64
#define BT_  (B_ * T_)

// Scratch Q/K/V stored as packed half2 words: [row][h2], 32 words per row
__device__ uint32_t g_q[BT_ * 32];
__device__ uint32_t g_k[BT_ * 32];
__device__ uint32_t g_v[BT_ * 32];

__device__ __forceinline__ uint32_t pk2(float lo, float hi) {
    __half2 h = __floats2half2_rn(lo, hi);
    return *(uint32_t*)&h;
}

// m16n8k16 fp16 mma, fp32 accumulate
__device__ __forceinline__ void mma16(float c[4], const uint32_t a[4], const uint32_t b[2]) {
    asm volatile(
        "mma.sync.aligned.m16n8k16.row.col.f32.f16.f16.f32 "
        "{%0,%1,%2,%3},{%4,%5,%6,%7},{%8,%9},{%0,%1,%2,%3};\n"
        : "+f"(c[0]), "+f"(c[1]), "+f"(c[2]), "+f"(c[3])
        : "r"(a[0]), "r"(a[1]), "r"(a[2]), "r"(a[3]), "r"(b[0]), "r"(b[1]));
}

#define CP16(dst_u32, src_ptr) \
    asm volatile("cp.async.cg.shared.global [%0], [%1], 16;\n" \
                 :: "r"(dst_u32), "l"(src_ptr))
#define CP_COMMIT() asm volatile("cp.async.commit_group;\n" ::)
#define CP_WAIT1()  asm volatile("cp.async.wait_group 1;\n" ::)
#define CP_WAIT0()  asm volatile("cp.async.wait_group 0;\n" ::)

// ---------------------------------------------------------------------------
// QKV projection (fp16 k16 mma): CTA tile 64x192, 256 threads (8 warps,
// 2m x 4n, warp tile 32x48), 2 CTAs/SM. cp.async fp32 double buffer;
// fp32 -> fp16 conversion at fragment load.
// ---------------------------------------------------------------------------
#define AS_ 36    // A smem row stride (floats), 64x32 tile
#define BS_ 200   // B smem row stride (floats), 32x192 tile
#define ASZ (64 * AS_)
#define BSZ (32 * BS_)
#define QKV_SMEM ((2 * ASZ + 2 * BSZ) * 4)

__global__ __launch_bounds__(256, 2) void qkv_mma_kernel(
    const float* __restrict__ inp,
    const float* __restrict__ Wv, const float* __restrict__ bv,
    const float* __restrict__ Wk, const float* __restrict__ bk,
    const float* __restrict__ Wq, const float* __restrict__ bq)
{
    extern __shared__ float smf[];
    float* As = smf;            // [2][ASZ]
    float* Bs = smf + 2 * ASZ;  // [2][BSZ]

    const int m0   = blockIdx.x * 64;
    const int tid  = threadIdx.x;
    const int lane = tid & 31;
    const int w    = tid >> 5;
    const int g    = lane >> 2;
    const int t4   = lane & 3;
    const int wm   = w >> 2;          // 0..1 -> 32-row slice
    const int wn   = w & 3;           // 0..3 -> 48-col slice

    // A: 512 float4 / 256 thr = 2 each
    const int ar0 = tid >> 3, ar1 = (tid + 256) >> 3, ac4 = tid & 7;
    // B: 1536 float4 / 256 thr = 6 each
    int br[6], bm[6], blc4[6];
    #pragma unroll
    for (int i = 0; i < 6; i++) {
        int j = tid + 256 * i;
        br[i] = j / 48;
        int c4 = j % 48;
        bm[i] = c4 >> 4;
        blc4[i] = c4 & 15;
    }
    const float* Ws[3] = { Wv, Wk, Wq };

    const uint32_t sA = (uint32_t)__cvta_generic_to_shared(As);
    const uint32_t sB = (uint32_t)__cvta_generic_to_shared(Bs);

    auto stage = [&](int buf, int k0) {
        uint32_t a_base = sA + buf * ASZ * 4;
        CP16(a_base + (ar0 * AS_ + ac4 * 4) * 4, &inp[(m0 + ar0) * C_ + k0 + ac4 * 4]);
        CP16(a_base + (ar1 * AS_ + ac4 * 4) * 4, &inp[(m0 + ar1) * C_ + k0 + ac4 * 4]);
        uint32_t b_base = sB + buf * BSZ * 4;
        #pragma unroll
        for (int i = 0; i < 6; i++)
            CP16(b_base + (br[i] * BS_ + (bm[i] * 16 + blc4[i]) * 4) * 4,
                 &Ws[bm[i]][(k0 + br[i]) * H_ + blc4[i] * 4]);
    };

    float acc[2][6][4] = {};

    stage(0, 0);
    CP_COMMIT();

    #pragma unroll 1
    for (int it = 0; it < 12; it++) {
        if (it + 1 < 12) { stage((it + 1) & 1, (it + 1) * 32); CP_COMMIT(); CP_WAIT1(); }
        else             { CP_WAIT0(); }
        __syncthreads();

        const float* Af = As + (it & 1) * ASZ;
        const float* Bf = Bs + (it & 1) * BSZ;

        #pragma unroll
        for (int ks = 0; ks < 2; ks++) {        // two k16 steps per 32-chunk
            const int kb = ks * 16;
            uint32_t a[2][4];
            #pragma unroll
            for (int fm = 0; fm < 2; fm++) {
                int rb = wm * 32 + fm * 16;
                float2 v0 = *(const float2*)&Af[(rb + g)     * AS_ + kb + 2 * t4];
                float2 v1 = *(const float2*)&Af[(rb + g + 8) * AS_ + kb + 2 * t4];
                float2 v2 = *(const float2*)&Af[(rb + g)     * AS_ + kb + 8 + 2 * t4];
                float2 v3 = *(const float2*)&Af[(rb + g + 8) * AS_ + kb + 8 + 2 * t4];
                a[fm][0] = pk2(v0.x, v0.y);
                a[fm][1] = pk2(v1.x, v1.y);
                a[fm][2] = pk2(v2.x, v2.y);
                a[fm][3] = pk2(v3.x, v3.y);
            }
            #pragma unroll
            for (int fn = 0; fn < 6; fn++) {
                int n = wn * 48 + fn * 8 + g;
                uint32_t b[2];
                b[0] = pk2(Bf[(kb + 2 * t4)     * BS_ + n], Bf[(kb + 2 * t4 + 1) * BS_ + n]);
                b[1] = pk2(Bf[(kb + 8 + 2 * t4) * BS_ + n], Bf[(kb + 9 + 2 * t4) * BS_ + n]);
                mma16(acc[0][fn], a[0], b);
                mma16(acc[1][fn], a[1], b);
            }
        }
        __syncthreads();
    }

    // epilogue: bias add, pack fp16, store half2 word
    #pragma unroll
    for (int fm = 0; fm < 2; fm++) {
        int r0 = m0 + wm * 32 + fm * 16 + g;
        #pragma unroll
        for (int fn = 0; fn < 6; fn++) {
            int gcol = wn * 48 + fn * 8 + 2 * t4;   // even
            int mtx  = gcol >> 6;
            int lc   = gcol & 63;
            uint32_t* op = (mtx == 0) ? g_v : (mtx == 1) ? g_k : g_q;
            const float* bp = (mtx == 0) ? bv : (mtx == 1) ? bk : bq;
            float b0f = bp[lc], b1f = bp[lc + 1];
            op[r0 * 32 + (lc >> 1)] =
                pk2(acc[fm][fn][0] + b0f, acc[fm][fn][1] + b1f);
            op[(r0 + 8) * 32 + (lc >> 1)] =
                pk2(acc[fm][fn][2] + b0f, acc[fm][fn][3] + b1f);
        }
    }
}

// ---------------------------------------------------------------------------
// FlashAttention-2, fp16 k16 mma. CTA = (batch, 128-row t-block), 256 thr.
// P C-frag -> PV A-frag is pure in-thread packing (no shuffles).
// ---------------------------------------------------------------------------
#define KR2 36   // Kr stride (half2 words)
#define QT2 36   // Qt stride
#define VT2 37   // Vt stride (odd: spreads transpose-store banks)

__global__ __launch_bounds__(256, 2) void attn_fa_kernel(float* __restrict__ out)
{
    extern __shared__ uint32_t sm[];
    uint32_t* Kr = sm;                 // [128][KR2] keys rows
    uint32_t* Qt = Kr + 128 * KR2;     // [64][QT2]  queries s-tile
    uint32_t* Vt = Qt + 64 * QT2;      // [64][VT2]  V transposed (h rows, s2 words)

    const int b    = blockIdx.x >> 1;
    const int t0   = (blockIdx.x & 1) * 128;
    const int tid  = threadIdx.x;
    const int lane = tid & 31;
    const int w    = tid >> 5;
    const int g    = lane >> 2;
    const int t4   = lane & 3;
    const int m0w  = w * 16;

    const int row0  = t0 + m0w + g;
    const int row1  = row0 + 8;
    const int tlast = t0 + m0w + 15;
    const int jmax  = tlast >> 6;

    const uint32_t* gk = g_k + b * T_ * 32;
    const uint32_t* gq = g_q + b * T_ * 32;
    const uint32_t* gv = g_v + b * T_ * 32;
    const float scale = 0.05103103630798288f;   // 384^-0.5

    const uint32_t vt_base = (uint32_t)__cvta_generic_to_shared(Vt);

    // stage keys tile [128][32 words]
    #pragma unroll
    for (int i = 0; i < 4; i++) {
        int j = tid + 256 * i;          // 1024 uint4
        int r = j >> 3, w4 = j & 7;
        *(uint4*)&Kr[r * KR2 + w4 * 4] = ((const uint4*)(gk + t0 * 32))[j];
    }

    float m_run0 = -1e30f, m_run1 = -1e30f;
    float l0 = 0.f, l1 = 0.f;
    float accO[8][4] = {};

    const int njt = (t0 + 128) >> 6;

    for (int jt = 0; jt < njt; jt++) {
        const int s0 = jt * 64;

        // stage Q tile [64][32 words]
        #pragma unroll
        for (int i = 0; i < 2; i++) {
            int j = tid + 256 * i;      // 512 uint4
            int r = j >> 3, w4 = j & 7;
            *(uint4*)&Qt[r * QT2 + w4 * 4] = ((const uint4*)(gq + s0 * 32))[j];
        }
        // stage V transposed: Vt[h][s2] from gv[s][h2]
        #pragma unroll
        for (int i = 0; i < 8; i++) {
            int j = tid + 256 * i;      // 2048 words
            int s = j >> 5, h2 = j & 31;
            uint32_t v = (gv + s0 * 32)[j];
            uint32_t off = (s & 1) * 2 + ((uint32_t)(s >> 1)) * 4;
            uint16_t vlo = (uint16_t)(v & 0xffffu);
            uint16_t vhi = (uint16_t)(v >> 16);
            asm volatile("st.shared.u16 [%0], %1;"
                         :: "r"(vt_base + (2 * h2) * VT2 * 4 + off), "h"(vlo) : "memory");
            asm volatile("st.shared.u16 [%0], %1;"
                         :: "r"(vt_base + (2 * h2 + 1) * VT2 * 4 + off), "h"(vhi) : "memory");
        }
        __syncthreads();

        if (jt <= jmax) {
            const int nf = min(8, ((tlast - s0) >> 3) + 1);   // always even
            const bool need_mask = (s0 + 63 > t0 + m0w);

            // ---- S = K_rows @ Q_tile^T ----
            float accS[8][4];
            #pragma unroll
            for (int fn = 0; fn < 8; fn++)
                #pragma unroll
                for (int e2 = 0; e2 < 4; e2++) accS[fn][e2] = 0.f;

            #pragma unroll
            for (int ks = 0; ks < 4; ks++) {
                const int kw = ks * 8;
                uint32_t a[4];
                a[0] = Kr[(m0w + g)     * KR2 + kw + t4];
                a[1] = Kr[(m0w + g + 8) * KR2 + kw + t4];
                a[2] = Kr[(m0w + g)     * KR2 + kw + t4 + 4];
                a[3] = Kr[(m0w + g + 8) * KR2 + kw + t4 + 4];
                for (int fn = 0; fn < nf; fn++) {
                    int n = fn * 8 + g;
                    uint32_t bb[2];
                    bb[0] = Qt[n * QT2 + kw + t4];
                    bb[1] = Qt[n * QT2 + kw + t4 + 4];
                    mma16(accS[fn], a, bb);
                }
            }

            // ---- causal mask ----
            if (need_mask) {
                for (int fn = 0; fn < nf; fn++) {
                    int c = s0 + fn * 8 + 2 * t4;
                    if (c     > row0) accS[fn][0] = -1e30f;
                    if (c + 1 > row0) accS[fn][1] = -1e30f;
                    if (c     > row1) accS[fn][2] = -1e30f;
                    if (c + 1 > row1) accS[fn][3] = -1e30f;
                }
            }

            // ---- row max (quad reduce) ----
            float mt0 = -1e30f, mt1 = -1e30f;
            for (int fn = 0; fn < nf; fn++) {
                mt0 = fmaxf(mt0, fmaxf(accS[fn][0], accS[fn][1]));
                mt1 = fmaxf(mt1, fmaxf(accS[fn][2], accS[fn][3]));
            }
            #pragma unroll
            for (int o = 1; o <= 2; o <<= 1) {
                mt0 = fmaxf(mt0, __shfl_xor_sync(0xffffffffu, mt0, o));
                mt1 = fmaxf(mt1, __shfl_xor_sync(0xffffffffu, mt1, o));
            }
            float mn0 = fmaxf(m_run0, mt0);
            float mn1 = fmaxf(m_run1, mt1);
            float al0 = __expf((m_run0 - mn0) * scale);
            float al1 = __expf((m_run1 - mn1) * scale);
            m_run0 = mn0; m_run1 = mn1;

            // ---- p = exp((s-m)*scale), sums, in-place fp16 A-frag pack ----
            float ts0 = 0.f, ts1 = 0.f;
            uint32_t pA[8][2];   // [fn] -> {pack(p0,p1), pack(p2,p3)}
            for (int fn = 0; fn < nf; fn++) {
                float p0 = __expf((accS[fn][0] - mn0) * scale);
                float p1 = __expf((accS[fn][1] - mn0) * scale);
                float p2 = __expf((accS[fn][2] - mn1) * scale);
                float p3 = __expf((accS[fn][3] - mn1) * scale);
                ts0 += p0 + p1; ts1 += p2 + p3;
                pA[fn][0] = pk2(p0, p1);
                pA[fn][1] = pk2(p2, p3);
            }
            #pragma unroll
            for (int o = 1; o <= 2; o <<= 1) {
                ts0 += __shfl_xor_sync(0xffffffffu, ts0, o);
                ts1 += __shfl_xor_sync(0xffffffffu, ts1, o);
            }
            l0 = l0 * al0 + ts0;
            l1 = l1 * al1 + ts1;

            // ---- rescale accO ----
            #pragma unroll
            for (int fn = 0; fn < 8; fn++) {
                accO[fn][0] *= al0; accO[fn][1] *= al0;
                accO[fn][2] *= al1; accO[fn][3] *= al1;
            }

            // ---- PV: A-frags in-thread; B from Vt ----
            const int nkc = nf >> 1;
            for (int kc = 0; kc < nkc; kc++) {
                uint32_t a[4];
                a[0] = pA[2 * kc][0];       // (row g,   s = 16kc + 2t4..)
                a[1] = pA[2 * kc][1];       // (row g+8, same)
                a[2] = pA[2 * kc + 1][0];   // (row g,   s = 16kc+8+2t4..)
                a[3] = pA[2 * kc + 1][1];   // (row g+8, same)
                const int kw = kc * 8;
                #pragma unroll
                for (int fn = 0; fn < 8; fn++) {
                    int n = fn * 8 + g;
                    uint32_t bb[2];
                    bb[0] = Vt[n * VT2 + kw + t4];
                    bb[1] = Vt[n * VT2 + kw + t4 + 4];
                    mma16(accO[fn], a, bb);
                }
            }
        }
        __syncthreads();
    }

    // epilogue: normalize + store fp32
    const float inv0 = 1.0f / l0;
    const float inv1 = 1.0f / l1;
    float* ob = out + (size_t)b * T_ * H_;
    #pragma unroll
    for (int fn = 0; fn < 8; fn++) {
        int c = fn * 8 + 2 * t4;
        *(float2*)&ob[row0 * H_ + c] =
            make_float2(accO[fn][0] * inv0, accO[fn][1] * inv0);
        *(float2*)&ob[row1 * H_ + c] =
            make_float2(accO[fn][2] * inv1, accO[fn][3] * inv1);
    }
}

// ---------------------------------------------------------------------------
extern "C" void kernel_launch(void* const* d_in, const int* in_sizes, int n_in,
                              void* d_out, int out_size)
{
    const float* inp = (const float*)d_in[0];
    const float* Wv  = (const float*)d_in[1];
    const float* bv  = (const float*)d_in[2];
    const float* Wk  = (const float*)d_in[3];
    const float* bk  = (const float*)d_in[4];
    const float* Wq  = (const float*)d_in[5];
    const float* bq  = (const float*)d_in[6];
    float* out = (float*)d_out;

    (void)in_sizes; (void)n_in; (void)out_size;

    cudaFuncSetAttribute(qkv_mma_kernel,
                         cudaFuncAttributeMaxDynamicSharedMemorySize, QKV_SMEM);
    qkv_mma_kernel<<<BT_ / 64, 256, QKV_SMEM>>>(inp, Wv, bv, Wk, bk, Wq, bq);

    const int attn_smem = (128 * KR2 + 64 * QT2 + 64 * VT2) * 4;
    cudaFuncSetAttribute(attn_fa_kernel,
                         cudaFuncAttributeMaxDynamicSharedMemorySize, attn_smem);
    attn_fa_kernel<<<B_ * 2, 256, attn_smem>>>(out);
}

// round 9
// speedup vs baseline: 1.4181x; 1.4181x over previous
#include <cuda_runtime.h>
#include <cuda_fp16.h>
#include <math.h>
#include <stdint.h>

#define B_   512
#define T_   256
#define C_   384
#define H_   64
#define BT_  (B_ * T_)

// Scratch Q/K/V stored as packed half2 words: [row][h2], 32 words per row
__device__ uint32_t g_q[BT_ * 32];
__device__ uint32_t g_k[BT_ * 32];
__device__ uint32_t g_v[BT_ * 32];
// Pre-packed transposed weights: [n(192)][k2(192)] half2 words
__device__ uint32_t g_Wt[192 * 192];

__device__ __forceinline__ uint32_t pk2(float lo, float hi) {
    __half2 h = __floats2half2_rn(lo, hi);
    return *(uint32_t*)&h;
}

// m16n8k16 fp16 mma, fp32 accumulate
__device__ __forceinline__ void mma16(float c[4], const uint32_t a[4], const uint32_t b[2]) {
    asm volatile(
        "mma.sync.aligned.m16n8k16.row.col.f32.f16.f16.f32 "
        "{%0,%1,%2,%3},{%4,%5,%6,%7},{%8,%9},{%0,%1,%2,%3};\n"
        : "+f"(c[0]), "+f"(c[1]), "+f"(c[2]), "+f"(c[3])
        : "r"(a[0]), "r"(a[1]), "r"(a[2]), "r"(a[3]), "r"(b[0]), "r"(b[1]));
}

#define CP16(dst_u32, src_ptr) \
    asm volatile("cp.async.cg.shared.global [%0], [%1], 16;\n" \
                 :: "r"(dst_u32), "l"(src_ptr))
#define CP_COMMIT() asm volatile("cp.async.commit_group;\n" ::)
#define CP_WAIT1()  asm volatile("cp.async.wait_group 1;\n" ::)
#define CP_WAIT0()  asm volatile("cp.async.wait_group 0;\n" ::)

// ---------------------------------------------------------------------------
// Weight prep: g_Wt[n][k2] = pack(W[2k2][n], W[2k2+1][n]); n in [0,192) spans
// [Wv|Wk|Wq] columns. Coalesced reads over n.
// ---------------------------------------------------------------------------
__global__ __launch_bounds__(512) void prep_wt_kernel(
    const float* __restrict__ Wv, const float* __restrict__ Wk,
    const float* __restrict__ Wq)
{
    int idx = blockIdx.x * 512 + threadIdx.x;   // 0..36863
    int k2 = idx / 192;
    int n  = idx - k2 * 192;
    int mtx = n >> 6, lc = n & 63;
    const float* Wm = (mtx == 0) ? Wv : (mtx == 1) ? Wk : Wq;
    g_Wt[n * 192 + k2] = pk2(Wm[(2 * k2) * H_ + lc], Wm[(2 * k2 + 1) * H_ + lc]);
}

// ---------------------------------------------------------------------------
// QKV projection (fp16 k16 mma, fp16-packed smem):
// CTA tile 64x192, 256 threads (8 warps, 2m x 4n, warp tile 32x48), 2 CTAs/SM.
// A: LDG.128 prefetch -> pack half2 -> STS. B: cp.async from g_Wt.
// Fragment loads are single LDS.32, conflict-free (stride 20 mod 32 trick).
// ---------------------------------------------------------------------------
#define AS2 20                 // A smem stride (words): 16 data + 4 pad
#define BS2 20                 // B smem stride (words)
#define ASZ2 (64 * AS2)        // 1280 words per buf
#define BSZ2 (192 * BS2)       // 3840 words per buf
#define QKV_SMEM ((2 * ASZ2 + 2 * BSZ2) * 4)   // 40960 B

__global__ __launch_bounds__(256, 2) void qkv_mma_kernel(
    const float* __restrict__ inp,
    const float* __restrict__ bv, const float* __restrict__ bk,
    const float* __restrict__ bq)
{
    extern __shared__ uint32_t smw[];
    uint32_t* Asw = smw;               // [2][ASZ2]
    uint32_t* Bsw = smw + 2 * ASZ2;    // [2][BSZ2]

    const int m0   = blockIdx.x * 64;
    const int tid  = threadIdx.x;
    const int lane = tid & 31;
    const int w    = tid >> 5;
    const int g    = lane >> 2;
    const int t4   = lane & 3;
    const int wm   = w >> 2;          // 0..1 -> 32-row slice
    const int wn   = w & 3;           // 0..3 -> 48-col slice

    // A LDG mapping: 512 float4 / 256 thr = 2 each
    const int ar0 = tid >> 3, ar1 = (tid + 256) >> 3, ac4 = tid & 7;

    const uint32_t sB = (uint32_t)__cvta_generic_to_shared(Bsw);

    auto stageB = [&](int buf, int c) {
        uint32_t b_base = sB + buf * BSZ2 * 4;
        #pragma unroll
        for (int i = 0; i < 3; i++) {
            int idx = tid + 256 * i;       // 0..767
            int n = idx >> 2, q = idx & 3;
            CP16(b_base + (n * BS2 + q * 4) * 4, g_Wt + n * 192 + c * 16 + q * 4);
        }
    };

    float4 aR[2];
    aR[0] = *(const float4*)&inp[(m0 + ar0) * C_ + ac4 * 4];
    aR[1] = *(const float4*)&inp[(m0 + ar1) * C_ + ac4 * 4];
    stageB(0, 0);
    CP_COMMIT();

    float acc[2][6][4] = {};

    #pragma unroll 1
    for (int c = 0; c < 12; c++) {
        const int buf = c & 1;

        if (c + 1 < 12) { stageB((c + 1) & 1, c + 1); CP_COMMIT(); CP_WAIT1(); }
        else            { CP_WAIT0(); }

        // commit A regs (pack to half2) into buf
        {
            uint32_t* Ab = Asw + buf * ASZ2;
            #pragma unroll
            for (int i = 0; i < 2; i++) {
                int r = i ? ar1 : ar0;
                float4 v = aR[i];
                *(uint2*)&Ab[r * AS2 + ac4 * 2] =
                    make_uint2(pk2(v.x, v.y), pk2(v.z, v.w));
            }
        }
        __syncthreads();

        // prefetch next A chunk
        if (c + 1 < 12) {
            const int k0n = (c + 1) * 32;
            aR[0] = *(const float4*)&inp[(m0 + ar0) * C_ + k0n + ac4 * 4];
            aR[1] = *(const float4*)&inp[(m0 + ar1) * C_ + k0n + ac4 * 4];
        }

        // compute chunk c: 2 k16 steps
        {
            const uint32_t* Af = Asw + buf * ASZ2;
            const uint32_t* Bf = Bsw + buf * BSZ2;
            #pragma unroll
            for (int ks = 0; ks < 2; ks++) {
                const int kw = ks * 8;
                uint32_t a[2][4];
                #pragma unroll
                for (int fm = 0; fm < 2; fm++) {
                    int rb = wm * 32 + fm * 16;
                    a[fm][0] = Af[(rb + g)     * AS2 + kw + t4];
                    a[fm][1] = Af[(rb + g + 8) * AS2 + kw + t4];
                    a[fm][2] = Af[(rb + g)     * AS2 + kw + t4 + 4];
                    a[fm][3] = Af[(rb + g + 8) * AS2 + kw + t4 + 4];
                }
                #pragma unroll
                for (int fn = 0; fn < 6; fn++) {
                    int n = wn * 48 + fn * 8 + g;
                    uint32_t b[2];
                    b[0] = Bf[n * BS2 + kw + t4];
                    b[1] = Bf[n * BS2 + kw + t4 + 4];
                    mma16(acc[0][fn], a[0], b);
                    mma16(acc[1][fn], a[1], b);
                }
            }
        }
        __syncthreads();
    }

    // epilogue: bias add, pack fp16, store half2 word
    #pragma unroll
    for (int fm = 0; fm < 2; fm++) {
        int r0 = m0 + wm * 32 + fm * 16 + g;
        #pragma unroll
        for (int fn = 0; fn < 6; fn++) {
            int gcol = wn * 48 + fn * 8 + 2 * t4;   // even
            int mtx  = gcol >> 6;
            int lc   = gcol & 63;
            uint32_t* op = (mtx == 0) ? g_v : (mtx == 1) ? g_k : g_q;
            const float* bp = (mtx == 0) ? bv : (mtx == 1) ? bk : bq;
            float b0f = bp[lc], b1f = bp[lc + 1];
            op[r0 * 32 + (lc >> 1)] =
                pk2(acc[fm][fn][0] + b0f, acc[fm][fn][1] + b1f);
            op[(r0 + 8) * 32 + (lc >> 1)] =
                pk2(acc[fm][fn][2] + b0f, acc[fm][fn][3] + b1f);
        }
    }
}

// ---------------------------------------------------------------------------
// FlashAttention-2, fp16 k16 mma (unchanged from R8; 47.9 us known-good).
// ---------------------------------------------------------------------------
#define KR2 36
#define QT2 36
#define VT2 37

__global__ __launch_bounds__(256, 2) void attn_fa_kernel(float* __restrict__ out)
{
    extern __shared__ uint32_t sm[];
    uint32_t* Kr = sm;
    uint32_t* Qt = Kr + 128 * KR2;
    uint32_t* Vt = Qt + 64 * QT2;

    const int b    = blockIdx.x >> 1;
    const int t0   = (blockIdx.x & 1) * 128;
    const int tid  = threadIdx.x;
    const int lane = tid & 31;
    const int w    = tid >> 5;
    const int g    = lane >> 2;
    const int t4   = lane & 3;
    const int m0w  = w * 16;

    const int row0  = t0 + m0w + g;
    const int row1  = row0 + 8;
    const int tlast = t0 + m0w + 15;
    const int jmax  = tlast >> 6;

    const uint32_t* gk = g_k + b * T_ * 32;
    const uint32_t* gq = g_q + b * T_ * 32;
    const uint32_t* gv = g_v + b * T_ * 32;
    const float scale = 0.05103103630798288f;

    const uint32_t vt_base = (uint32_t)__cvta_generic_to_shared(Vt);

    #pragma unroll
    for (int i = 0; i < 4; i++) {
        int j = tid + 256 * i;
        int r = j >> 3, w4 = j & 7;
        *(uint4*)&Kr[r * KR2 + w4 * 4] = ((const uint4*)(gk + t0 * 32))[j];
    }

    float m_run0 = -1e30f, m_run1 = -1e30f;
    float l0 = 0.f, l1 = 0.f;
    float accO[8][4] = {};

    const int njt = (t0 + 128) >> 6;

    for (int jt = 0; jt < njt; jt++) {
        const int s0 = jt * 64;

        #pragma unroll
        for (int i = 0; i < 2; i++) {
            int j = tid + 256 * i;
            int r = j >> 3, w4 = j & 7;
            *(uint4*)&Qt[r * QT2 + w4 * 4] = ((const uint4*)(gq + s0 * 32))[j];
        }
        #pragma unroll
        for (int i = 0; i < 8; i++) {
            int j = tid + 256 * i;
            int s = j >> 5, h2 = j & 31;
            uint32_t v = (gv + s0 * 32)[j];
            uint32_t off = (s & 1) * 2 + ((uint32_t)(s >> 1)) * 4;
            uint16_t vlo = (uint16_t)(v & 0xffffu);
            uint16_t vhi = (uint16_t)(v >> 16);
            asm volatile("st.shared.u16 [%0], %1;"
                         :: "r"(vt_base + (2 * h2) * VT2 * 4 + off), "h"(vlo) : "memory");
            asm volatile("st.shared.u16 [%0], %1;"
                         :: "r"(vt_base + (2 * h2 + 1) * VT2 * 4 + off), "h"(vhi) : "memory");
        }
        __syncthreads();

        if (jt <= jmax) {
            const int nf = min(8, ((tlast - s0) >> 3) + 1);
            const bool need_mask = (s0 + 63 > t0 + m0w);

            float accS[8][4];
            #pragma unroll
            for (int fn = 0; fn < 8; fn++)
                #pragma unroll
                for (int e2 = 0; e2 < 4; e2++) accS[fn][e2] = 0.f;

            #pragma unroll
            for (int ks = 0; ks < 4; ks++) {
                const int kw = ks * 8;
                uint32_t a[4];
                a[0] = Kr[(m0w + g)     * KR2 + kw + t4];
                a[1] = Kr[(m0w + g + 8) * KR2 + kw + t4];
                a[2] = Kr[(m0w + g)     * KR2 + kw + t4 + 4];
                a[3] = Kr[(m0w + g + 8) * KR2 + kw + t4 + 4];
                for (int fn = 0; fn < nf; fn++) {
                    int n = fn * 8 + g;
                    uint32_t bb[2];
                    bb[0] = Qt[n * QT2 + kw + t4];
                    bb[1] = Qt[n * QT2 + kw + t4 + 4];
                    mma16(accS[fn], a, bb);
                }
            }

            if (need_mask) {
                for (int fn = 0; fn < nf; fn++) {
                    int c = s0 + fn * 8 + 2 * t4;
                    if (c     > row0) accS[fn][0] = -1e30f;
                    if (c + 1 > row0) accS[fn][1] = -1e30f;
                    if (c     > row1) accS[fn][2] = -1e30f;
                    if (c + 1 > row1) accS[fn][3] = -1e30f;
                }
            }

            float mt0 = -1e30f, mt1 = -1e30f;
            for (int fn = 0; fn < nf; fn++) {
                mt0 = fmaxf(mt0, fmaxf(accS[fn][0], accS[fn][1]));
                mt1 = fmaxf(mt1, fmaxf(accS[fn][2], accS[fn][3]));
            }
            #pragma unroll
            for (int o = 1; o <= 2; o <<= 1) {
                mt0 = fmaxf(mt0, __shfl_xor_sync(0xffffffffu, mt0, o));
                mt1 = fmaxf(mt1, __shfl_xor_sync(0xffffffffu, mt1, o));
            }
            float mn0 = fmaxf(m_run0, mt0);
            float mn1 = fmaxf(m_run1, mt1);
            float al0 = __expf((m_run0 - mn0) * scale);
            float al1 = __expf((m_run1 - mn1) * scale);
            m_run0 = mn0; m_run1 = mn1;

            float ts0 = 0.f, ts1 = 0.f;
            uint32_t pA[8][2];
            for (int fn = 0; fn < nf; fn++) {
                float p0 = __expf((accS[fn][0] - mn0) * scale);
                float p1 = __expf((accS[fn][1] - mn0) * scale);
                float p2 = __expf((accS[fn][2] - mn1) * scale);
                float p3 = __expf((accS[fn][3] - mn1) * scale);
                ts0 += p0 + p1; ts1 += p2 + p3;
                pA[fn][0] = pk2(p0, p1);
                pA[fn][1] = pk2(p2, p3);
            }
            #pragma unroll
            for (int o = 1; o <= 2; o <<= 1) {
                ts0 += __shfl_xor_sync(0xffffffffu, ts0, o);
                ts1 += __shfl_xor_sync(0xffffffffu, ts1, o);
            }
            l0 = l0 * al0 + ts0;
            l1 = l1 * al1 + ts1;

            #pragma unroll
            for (int fn = 0; fn < 8; fn++) {
                accO[fn][0] *= al0; accO[fn][1] *= al0;
                accO[fn][2] *= al1; accO[fn][3] *= al1;
            }

            const int nkc = nf >> 1;
            for (int kc = 0; kc < nkc; kc++) {
                uint32_t a[4];
                a[0] = pA[2 * kc][0];
                a[1] = pA[2 * kc][1];
                a[2] = pA[2 * kc + 1][0];
                a[3] = pA[2 * kc + 1][1];
                const int kw = kc * 8;
                #pragma unroll
                for (int fn = 0; fn < 8; fn++) {
                    int n = fn * 8 + g;
                    uint32_t bb[2];
                    bb[0] = Vt[n * VT2 + kw + t4];
                    bb[1] = Vt[n * VT2 + kw + t4 + 4];
                    mma16(accO[fn], a, bb);
                }
            }
        }
        __syncthreads();
    }

    const float inv0 = 1.0f / l0;
    const float inv1 = 1.0f / l1;
    float* ob = out + (size_t)b * T_ * H_;
    #pragma unroll
    for (int fn = 0; fn < 8; fn++) {
        int c = fn * 8 + 2 * t4;
        *(float2*)&ob[row0 * H_ + c] =
            make_float2(accO[fn][0] * inv0, accO[fn][1] * inv0);
        *(float2*)&ob[row1 * H_ + c] =
            make_float2(accO[fn][2] * inv1, accO[fn][3] * inv1);
    }
}

// ---------------------------------------------------------------------------
extern "C" void kernel_launch(void* const* d_in, const int* in_sizes, int n_in,
                              void* d_out, int out_size)
{
    const float* inp = (const float*)d_in[0];
    const float* Wv  = (const float*)d_in[1];
    const float* bv  = (const float*)d_in[2];
    const float* Wk  = (const float*)d_in[3];
    const float* bk  = (const float*)d_in[4];
    const float* Wq  = (const float*)d_in[5];
    const float* bq  = (const float*)d_in[6];
    float* out = (float*)d_out;

    (void)in_sizes; (void)n_in; (void)out_size;

    prep_wt_kernel<<<72, 512>>>(Wv, Wk, Wq);

    cudaFuncSetAttribute(qkv_mma_kernel,
                         cudaFuncAttributeMaxDynamicSharedMemorySize, QKV_SMEM);
    qkv_mma_kernel<<<BT_ / 64, 256, QKV_SMEM>>>(inp, bv, bk, bq);

    const int attn_smem = (128 * KR2 + 64 * QT2 + 64 * VT2) * 4;
    cudaFuncSetAttribute(attn_fa_kernel,
                         cudaFuncAttributeMaxDynamicSharedMemorySize, attn_smem);
    attn_fa_kernel<<<B_ * 2, 256, attn_smem>>>(out);
}

// round 10
// speedup vs baseline: 1.4757x; 1.0406x over previous
#include <cuda_runtime.h>
#include <cuda_fp16.h>
#include <math.h>
#include <stdint.h>

#define B_   512
#define T_   256
#define C_   384
#define H_   64
#define BT_  (B_ * T_)

// Scratch Q/K/V stored as packed half2 words: [row][h2], 32 words per row
__device__ uint32_t g_q[BT_ * 32];
__device__ uint32_t g_k[BT_ * 32];
__device__ uint32_t g_v[BT_ * 32];
// Pre-packed transposed weights: [n(192)][k2(192)] half2 words
__device__ uint32_t g_Wt[192 * 192];

__device__ __forceinline__ uint32_t pk2(float lo, float hi) {
    __half2 h = __floats2half2_rn(lo, hi);
    return *(uint32_t*)&h;
}

// m16n8k16 fp16 mma, fp32 accumulate
__device__ __forceinline__ void mma16(float c[4], const uint32_t a[4], const uint32_t b[2]) {
    asm volatile(
        "mma.sync.aligned.m16n8k16.row.col.f32.f16.f16.f32 "
        "{%0,%1,%2,%3},{%4,%5,%6,%7},{%8,%9},{%0,%1,%2,%3};\n"
        : "+f"(c[0]), "+f"(c[1]), "+f"(c[2]), "+f"(c[3])
        : "r"(a[0]), "r"(a[1]), "r"(a[2]), "r"(a[3]), "r"(b[0]), "r"(b[1]));
}

#define CP16(dst_u32, src_ptr) \
    asm volatile("cp.async.cg.shared.global [%0], [%1], 16;\n" \
                 :: "r"(dst_u32), "l"(src_ptr))
#define CP_COMMIT() asm volatile("cp.async.commit_group;\n" ::)
#define CP_WAIT1()  asm volatile("cp.async.wait_group 1;\n" ::)
#define CP_WAIT0()  asm volatile("cp.async.wait_group 0;\n" ::)

// ---------------------------------------------------------------------------
// Weight prep: g_Wt[n][k2] = pack(W[2k2][n], W[2k2+1][n])
// ---------------------------------------------------------------------------
__global__ __launch_bounds__(512) void prep_wt_kernel(
    const float* __restrict__ Wv, const float* __restrict__ Wk,
    const float* __restrict__ Wq)
{
    int idx = blockIdx.x * 512 + threadIdx.x;   // 0..36863
    int k2 = idx / 192;
    int n  = idx - k2 * 192;
    int mtx = n >> 6, lc = n & 63;
    const float* Wm = (mtx == 0) ? Wv : (mtx == 1) ? Wk : Wq;
    g_Wt[n * 192 + k2] = pk2(Wm[(2 * k2) * H_ + lc], Wm[(2 * k2 + 1) * H_ + lc]);
}

// ---------------------------------------------------------------------------
// QKV projection (fp16 k16 mma): CTA tile 64x192, 128 threads (4 warps,
// 1m x 4n, warp tile 64x48), 3 CTAs/SM. Per k16 step: 24 mma / 28 LDS.
// ---------------------------------------------------------------------------
#define AS2 20                 // A smem stride (words)
#define BS2 20                 // B smem stride (words)
#define ASZ2 (64 * AS2)        // 1280 words per buf
#define BSZ2 (192 * BS2)       // 3840 words per buf
#define QKV_SMEM ((2 * ASZ2 + 2 * BSZ2) * 4)   // 40960 B

__global__ __launch_bounds__(128, 3) void qkv_mma_kernel(
    const float* __restrict__ inp,
    const float* __restrict__ bv, const float* __restrict__ bk,
    const float* __restrict__ bq)
{
    extern __shared__ uint32_t smw[];
    uint32_t* Asw = smw;               // [2][ASZ2]
    uint32_t* Bsw = smw + 2 * ASZ2;    // [2][BSZ2]

    const int m0   = blockIdx.x * 64;
    const int tid  = threadIdx.x;
    const int lane = tid & 31;
    const int w    = tid >> 5;        // 0..3
    const int g    = lane >> 2;
    const int t4   = lane & 3;
    const int wn   = w;               // 48-col slice

    // A LDG mapping: 512 float4 / 128 thr = 4 each
    const int arr[4] = { tid >> 3, (tid + 128) >> 3, (tid + 256) >> 3, (tid + 384) >> 3 };
    const int ac4 = tid & 7;

    const uint32_t sB = (uint32_t)__cvta_generic_to_shared(Bsw);

    auto stageB = [&](int buf, int c) {
        uint32_t b_base = sB + buf * BSZ2 * 4;
        #pragma unroll
        for (int i = 0; i < 6; i++) {
            int idx = tid + 128 * i;       // 0..767
            int n = idx >> 2, q = idx & 3;
            CP16(b_base + (n * BS2 + q * 4) * 4, g_Wt + n * 192 + c * 16 + q * 4);
        }
    };

    float4 aR[4];
    #pragma unroll
    for (int i = 0; i < 4; i++)
        aR[i] = *(const float4*)&inp[(m0 + arr[i]) * C_ + ac4 * 4];
    stageB(0, 0);
    CP_COMMIT();

    float acc[4][6][4] = {};

    #pragma unroll 1
    for (int c = 0; c < 12; c++) {
        const int buf = c & 1;

        if (c + 1 < 12) { stageB((c + 1) & 1, c + 1); CP_COMMIT(); CP_WAIT1(); }
        else            { CP_WAIT0(); }

        // commit A regs (pack to half2) into buf
        {
            uint32_t* Ab = Asw + buf * ASZ2;
            #pragma unroll
            for (int i = 0; i < 4; i++) {
                float4 v = aR[i];
                *(uint2*)&Ab[arr[i] * AS2 + ac4 * 2] =
                    make_uint2(pk2(v.x, v.y), pk2(v.z, v.w));
            }
        }
        __syncthreads();

        // prefetch next A chunk
        if (c + 1 < 12) {
            const int k0n = (c + 1) * 32;
            #pragma unroll
            for (int i = 0; i < 4; i++)
                aR[i] = *(const float4*)&inp[(m0 + arr[i]) * C_ + k0n + ac4 * 4];
        }

        // compute chunk c: 2 k16 steps x (4 fm x 6 fn) mma
        {
            const uint32_t* Af = Asw + buf * ASZ2;
            const uint32_t* Bf = Bsw + buf * BSZ2;
            #pragma unroll
            for (int ks = 0; ks < 2; ks++) {
                const int kw = ks * 8;
                uint32_t a[4][4];
                #pragma unroll
                for (int fm = 0; fm < 4; fm++) {
                    int rb = fm * 16;
                    a[fm][0] = Af[(rb + g)     * AS2 + kw + t4];
                    a[fm][1] = Af[(rb + g + 8) * AS2 + kw + t4];
                    a[fm][2] = Af[(rb + g)     * AS2 + kw + t4 + 4];
                    a[fm][3] = Af[(rb + g + 8) * AS2 + kw + t4 + 4];
                }
                #pragma unroll
                for (int fn = 0; fn < 6; fn++) {
                    int n = wn * 48 + fn * 8 + g;
                    uint32_t b[2];
                    b[0] = Bf[n * BS2 + kw + t4];
                    b[1] = Bf[n * BS2 + kw + t4 + 4];
                    #pragma unroll
                    for (int fm = 0; fm < 4; fm++)
                        mma16(acc[fm][fn], a[fm], b);
                }
            }
        }
        __syncthreads();
    }

    // epilogue: bias add, pack fp16, store half2 word
    #pragma unroll
    for (int fm = 0; fm < 4; fm++) {
        int r0 = m0 + fm * 16 + g;
        #pragma unroll
        for (int fn = 0; fn < 6; fn++) {
            int gcol = wn * 48 + fn * 8 + 2 * t4;   // even
            int mtx  = gcol >> 6;
            int lc   = gcol & 63;
            uint32_t* op = (mtx == 0) ? g_v : (mtx == 1) ? g_k : g_q;
            const float* bp = (mtx == 0) ? bv : (mtx == 1) ? bk : bq;
            float b0f = bp[lc], b1f = bp[lc + 1];
            op[r0 * 32 + (lc >> 1)] =
                pk2(acc[fm][fn][0] + b0f, acc[fm][fn][1] + b1f);
            op[(r0 + 8) * 32 + (lc >> 1)] =
                pk2(acc[fm][fn][2] + b0f, acc[fm][fn][3] + b1f);
        }
    }
}

// ---------------------------------------------------------------------------
// FlashAttention-2, fp16 k16 mma (unchanged; 47.9 us known-good).
// ---------------------------------------------------------------------------
#define KR2 36
#define QT2 36
#define VT2 37

__global__ __launch_bounds__(256, 2) void attn_fa_kernel(float* __restrict__ out)
{
    extern __shared__ uint32_t sm[];
    uint32_t* Kr = sm;
    uint32_t* Qt = Kr + 128 * KR2;
    uint32_t* Vt = Qt + 64 * QT2;

    const int b    = blockIdx.x >> 1;
    const int t0   = (blockIdx.x & 1) * 128;
    const int tid  = threadIdx.x;
    const int lane = tid & 31;
    const int w    = tid >> 5;
    const int g    = lane >> 2;
    const int t4   = lane & 3;
    const int m0w  = w * 16;

    const int row0  = t0 + m0w + g;
    const int row1  = row0 + 8;
    const int tlast = t0 + m0w + 15;
    const int jmax  = tlast >> 6;

    const uint32_t* gk = g_k + b * T_ * 32;
    const uint32_t* gq = g_q + b * T_ * 32;
    const uint32_t* gv = g_v + b * T_ * 32;
    const float scale = 0.05103103630798288f;

    const uint32_t vt_base = (uint32_t)__cvta_generic_to_shared(Vt);

    #pragma unroll
    for (int i = 0; i < 4; i++) {
        int j = tid + 256 * i;
        int r = j >> 3, w4 = j & 7;
        *(uint4*)&Kr[r * KR2 + w4 * 4] = ((const uint4*)(gk + t0 * 32))[j];
    }

    float m_run0 = -1e30f, m_run1 = -1e30f;
    float l0 = 0.f, l1 = 0.f;
    float accO[8][4] = {};

    const int njt = (t0 + 128) >> 6;

    for (int jt = 0; jt < njt; jt++) {
        const int s0 = jt * 64;

        #pragma unroll
        for (int i = 0; i < 2; i++) {
            int j = tid + 256 * i;
            int r = j >> 3, w4 = j & 7;
            *(uint4*)&Qt[r * QT2 + w4 * 4] = ((const uint4*)(gq + s0 * 32))[j];
        }
        #pragma unroll
        for (int i = 0; i < 8; i++) {
            int j = tid + 256 * i;
            int s = j >> 5, h2 = j & 31;
            uint32_t v = (gv + s0 * 32)[j];
            uint32_t off = (s & 1) * 2 + ((uint32_t)(s >> 1)) * 4;
            uint16_t vlo = (uint16_t)(v & 0xffffu);
            uint16_t vhi = (uint16_t)(v >> 16);
            asm volatile("st.shared.u16 [%0], %1;"
                         :: "r"(vt_base + (2 * h2) * VT2 * 4 + off), "h"(vlo) : "memory");
            asm volatile("st.shared.u16 [%0], %1;"
                         :: "r"(vt_base + (2 * h2 + 1) * VT2 * 4 + off), "h"(vhi) : "memory");
        }
        __syncthreads();

        if (jt <= jmax) {
            const int nf = min(8, ((tlast - s0) >> 3) + 1);
            const bool need_mask = (s0 + 63 > t0 + m0w);

            float accS[8][4];
            #pragma unroll
            for (int fn = 0; fn < 8; fn++)
                #pragma unroll
                for (int e2 = 0; e2 < 4; e2++) accS[fn][e2] = 0.f;

            #pragma unroll
            for (int ks = 0; ks < 4; ks++) {
                const int kw = ks * 8;
                uint32_t a[4];
                a[0] = Kr[(m0w + g)     * KR2 + kw + t4];
                a[1] = Kr[(m0w + g + 8) * KR2 + kw + t4];
                a[2] = Kr[(m0w + g)     * KR2 + kw + t4 + 4];
                a[3] = Kr[(m0w + g + 8) * KR2 + kw + t4 + 4];
                for (int fn = 0; fn < nf; fn++) {
                    int n = fn * 8 + g;
                    uint32_t bb[2];
                    bb[0] = Qt[n * QT2 + kw + t4];
                    bb[1] = Qt[n * QT2 + kw + t4 + 4];
                    mma16(accS[fn], a, bb);
                }
            }

            if (need_mask) {
                for (int fn = 0; fn < nf; fn++) {
                    int c = s0 + fn * 8 + 2 * t4;
                    if (c     > row0) accS[fn][0] = -1e30f;
                    if (c + 1 > row0) accS[fn][1] = -1e30f;
                    if (c     > row1) accS[fn][2] = -1e30f;
                    if (c + 1 > row1) accS[fn][3] = -1e30f;
                }
            }

            float mt0 = -1e30f, mt1 = -1e30f;
            for (int fn = 0; fn < nf; fn++) {
                mt0 = fmaxf(mt0, fmaxf(accS[fn][0], accS[fn][1]));
                mt1 = fmaxf(mt1, fmaxf(accS[fn][2], accS[fn][3]));
            }
            #pragma unroll
            for (int o = 1; o <= 2; o <<= 1) {
                mt0 = fmaxf(mt0, __shfl_xor_sync(0xffffffffu, mt0, o));
                mt1 = fmaxf(mt1, __shfl_xor_sync(0xffffffffu, mt1, o));
            }
            float mn0 = fmaxf(m_run0, mt0);
            float mn1 = fmaxf(m_run1, mt1);
            float al0 = __expf((m_run0 - mn0) * scale);
            float al1 = __expf((m_run1 - mn1) * scale);
            m_run0 = mn0; m_run1 = mn1;

            float ts0 = 0.f, ts1 = 0.f;
            uint32_t pA[8][2];
            for (int fn = 0; fn < nf; fn++) {
                float p0 = __expf((accS[fn][0] - mn0) * scale);
                float p1 = __expf((accS[fn][1] - mn0) * scale);
                float p2 = __expf((accS[fn][2] - mn1) * scale);
                float p3 = __expf((accS[fn][3] - mn1) * scale);
                ts0 += p0 + p1; ts1 += p2 + p3;
                pA[fn][0] = pk2(p0, p1);
                pA[fn][1] = pk2(p2, p3);
            }
            #pragma unroll
            for (int o = 1; o <= 2; o <<= 1) {
                ts0 += __shfl_xor_sync(0xffffffffu, ts0, o);
                ts1 += __shfl_xor_sync(0xffffffffu, ts1, o);
            }
            l0 = l0 * al0 + ts0;
            l1 = l1 * al1 + ts1;

            #pragma unroll
            for (int fn = 0; fn < 8; fn++) {
                accO[fn][0] *= al0; accO[fn][1] *= al0;
                accO[fn][2] *= al1; accO[fn][3] *= al1;
            }

            const int nkc = nf >> 1;
            for (int kc = 0; kc < nkc; kc++) {
                uint32_t a[4];
                a[0] = pA[2 * kc][0];
                a[1] = pA[2 * kc][1];
                a[2] = pA[2 * kc + 1][0];
                a[3] = pA[2 * kc + 1][1];
                const int kw = kc * 8;
                #pragma unroll
                for (int fn = 0; fn < 8; fn++) {
                    int n = fn * 8 + g;
                    uint32_t bb[2];
                    bb[0] = Vt[n * VT2 + kw + t4];
                    bb[1] = Vt[n * VT2 + kw + t4 + 4];
                    mma16(accO[fn], a, bb);
                }
            }
        }
        __syncthreads();
    }

    const float inv0 = 1.0f / l0;
    const float inv1 = 1.0f / l1;
    float* ob = out + (size_t)b * T_ * H_;
    #pragma unroll
    for (int fn = 0; fn < 8; fn++) {
        int c = fn * 8 + 2 * t4;
        *(float2*)&ob[row0 * H_ + c] =
            make_float2(accO[fn][0] * inv0, accO[fn][1] * inv0);
        *(float2*)&ob[row1 * H_ + c] =
            make_float2(accO[fn][2] * inv1, accO[fn][3] * inv1);
    }
}

// ---------------------------------------------------------------------------
extern "C" void kernel_launch(void* const* d_in, const int* in_sizes, int n_in,
                              void* d_out, int out_size)
{
    const float* inp = (const float*)d_in[0];
    const float* Wv  = (const float*)d_in[1];
    const float* bv  = (const float*)d_in[2];
    const float* Wk  = (const float*)d_in[3];
    const float* bk  = (const float*)d_in[4];
    const float* Wq  = (const float*)d_in[5];
    const float* bq  = (const float*)d_in[6];
    float* out = (float*)d_out;

    (void)in_sizes; (void)n_in; (void)out_size;

    prep_wt_kernel<<<72, 512>>>(Wv, Wk, Wq);

    cudaFuncSetAttribute(qkv_mma_kernel,
                         cudaFuncAttributeMaxDynamicSharedMemorySize, QKV_SMEM);
    qkv_mma_kernel<<<BT_ / 64, 128, QKV_SMEM>>>(inp, bv, bk, bq);

    const int attn_smem = (128 * KR2 + 64 * QT2 + 64 * VT2) * 4;
    cudaFuncSetAttribute(attn_fa_kernel,
                         cudaFuncAttributeMaxDynamicSharedMemorySize, attn_smem);
    attn_fa_kernel<<<B_ * 2, 256, attn_smem>>>(out);
}